// round 16
// baseline (speedup 1.0000x reference)
#include <cuda_runtime.h>
#include <cuda_fp16.h>
#include <math.h>
#include <stdint.h>

// ---------------- problem constants ----------------
#define Bz   8
#define Cz   8
#define Tz   2048
#define Fz   257
#define Hz   256
#define NHz  4
#define DHz  64
#define WINz 512
#define HSz  128
#define M2   (Bz*Tz)        // 16384 rows
#define BTF  (M2*Fz)

// ---------------- device scratch ----------------
__device__ __align__(16) float g_lin1 [M2*Hz];
__device__ __align__(16) float g_q    [M2*Hz];
__device__ __align__(16) float g_k    [Cz*M2*Hz];
__device__ __align__(16) float g_v    [Cz*M2*Hz];
__device__ __align__(16) float g_h1pre[M2*Hz];
__device__ __align__(16) float g_h1   [M2*Hz];
__device__ __align__(16) float g_hhpre[M2*Hz];
__device__ __align__(16) float g_hh   [M2*Hz];
__device__ __align__(16) float g_s1   [M2*HSz];
__device__ __align__(16) float g_outacc[M2*Hz];
__device__ float g_cum[M2], g_rem[M2], g_still[M2], g_pc[M2];
__device__ __align__(16) float g_bqkv[768];
__device__ float g_gate[1];
__device__ int   g_any[1];
__device__ int   g_done[1];
__device__ int   g_any2[8];     // per-iteration alive flags (tail kernel)
__device__ int   g_bar2[64];    // grid-barrier counters for tail kernel

// fp16 hi/lo activation copies (GEMM A operands)
__device__ __align__(16) __half g_lin1_h[M2*Hz], g_lin1_l[M2*Hz];
__device__ __align__(16) __half g_ctx_h [M2*Hz], g_ctx_l [M2*Hz];
__device__ __align__(16) __half g_h1_h  [M2*Hz], g_h1_l  [M2*Hz];
__device__ __align__(16) __half g_f1_h  [M2*WINz], g_f1_l[M2*WINz];
__device__ __align__(16) __half g_hh_h  [M2*Hz], g_hh_l  [M2*Hz];

// transposed + fp16-split weights: Bt[n][k], zero padded
__device__ __align__(16) __half g_bt_in_hi [256*288],  g_bt_in_lo [256*288];
__device__ __align__(16) __half g_bt_qkv_hi[768*256],  g_bt_qkv_lo[768*256];
__device__ __align__(16) __half g_bt_o_hi  [256*256],  g_bt_o_lo  [256*256];
__device__ __align__(16) __half g_bt_f1_hi [512*256],  g_bt_f1_lo [512*256];
__device__ __align__(16) __half g_bt_f2_hi [256*512],  g_bt_f2_lo [256*512];
__device__ __align__(16) __half g_bt_s1_hi [128*256],  g_bt_s1_lo [128*256];
__device__ __align__(16) __half g_bt_out_hi[256*256],  g_bt_out_lo[256*256];  // cols 0..255

// ---------------- helpers ----------------
__device__ __forceinline__ uint32_t smem_u32(const void* p){
    uint32_t a;
    asm("{ .reg .u64 t; cvta.to.shared.u64 t, %1; cvt.u32.u64 %0, t; }" : "=r"(a) : "l"(p));
    return a;
}
#define CP_ASYNC16(dst, src) asm volatile("cp.async.ca.shared.global [%0], [%1], 16;" :: "r"(dst), "l"(src))
#define CP_COMMIT() asm volatile("cp.async.commit_group;" ::: "memory")
#define CP_WAIT0()  asm volatile("cp.async.wait_group 0;" ::: "memory")

#define LDSM4(r0,r1,r2,r3,addr) asm volatile( \
    "ldmatrix.sync.aligned.m8n8.x4.shared.b16 {%0,%1,%2,%3}, [%4];" \
    : "=r"(r0),"=r"(r1),"=r"(r2),"=r"(r3) : "r"(addr))

__device__ __forceinline__ void mma_f16(float& d0, float& d1, float& d2, float& d3,
                                        uint32_t a0, uint32_t a1, uint32_t a2, uint32_t a3,
                                        uint32_t b0, uint32_t b1){
    asm volatile("mma.sync.aligned.m16n8k16.row.col.f32.f16.f16.f32 "
        "{%0,%1,%2,%3}, {%4,%5,%6,%7}, {%8,%9}, {%0,%1,%2,%3};"
        : "+f"(d0), "+f"(d1), "+f"(d2), "+f"(d3)
        : "r"(a0), "r"(a1), "r"(a2), "r"(a3), "r"(b0), "r"(b1));
}
__device__ __forceinline__ uint32_t pack2(__half x, __half y){
    __half2 h = __halves2half2(x, y);
    return *(uint32_t*)&h;
}

// grid-wide barrier for the tail kernel (all 256 CTAs co-resident at 2 CTA/SM)
__device__ __forceinline__ void grid_bar2(int slot){
    __syncthreads();
    if (threadIdx.x == 0){
        __threadfence();
        atomicAdd(&g_bar2[slot], 1);
        while (*(volatile int*)&g_bar2[slot] < (int)gridDim.x) { }
        __threadfence();
    }
    __syncthreads();
}

// ---------------- GEMM core (device fn, 3xFP16 split, term-major ILP) ----------------
#define PITCH_H 40
#define MAT_H   (128*PITCH_H)
#define BUFF_H  (4*MAT_H)
#define SMEM_DYN (2*BUFF_H*2)    // 81920 bytes

template<int AK, bool RELU, bool HAS_RES, bool QKV, bool OUT32, bool OUT16>
__device__ void gemm_dev(const float* __restrict__ Af,
        const __half* __restrict__ Ah, const __half* __restrict__ Al,
        const __half* __restrict__ Bhi, const __half* __restrict__ Blo,
        const float* __restrict__ bias, const float* __restrict__ Res,
        float* __restrict__ Out0, float* __restrict__ Out1, float* __restrict__ Out2,
        __half* __restrict__ O16h, __half* __restrict__ O16l,
        int N, int ldD, int Ka, int Kb, int Kt, int chan, int bm0, int n0, __half* smh)
{
    const int tid  = threadIdx.x;
    const int wid  = tid >> 5;
    const int lane = tid & 31;
    const int g    = lane >> 2;
    const int t    = lane & 3;
    const int lq   = lane & 7;
    const int quad = lane >> 3;
    const int wm   = wid & 1;
    const int wn   = wid >> 1;

    const int a_off = (wm * 64 + lq + (quad & 1) * 8) * PITCH_H + (quad >> 1) * 8;
    const int b_off = (wn * 32 + (quad >> 1) * 8 + lq) * PITCH_H + (quad & 1) * 8;

    float acc[4][4][4];
    #pragma unroll
    for (int i = 0; i < 4; i++)
        #pragma unroll
        for (int j = 0; j < 4; j++)
            #pragma unroll
            for (int r = 0; r < 4; r++) acc[i][j][r] = 0.f;

    auto loadA = [&](int kt, int buf){
        const int k0 = kt * 32;
        if (AK == 2) {
            const uint32_t ah = smem_u32(smh + buf * BUFF_H);
            const uint32_t al = ah + MAT_H * 2;
            #pragma unroll
            for (int it = 0; it < 2; it++) {
                const int idx = tid + it * 256;
                const int row = idx >> 2;
                const int c   = idx & 3;
                const uint32_t d = (uint32_t)((row * PITCH_H + c * 8) * 2);
                const long srco = (long)(bm0 + row) * Ka + k0 + c * 8;
                CP_ASYNC16(ah + d, Ah + srco);
                CP_ASYNC16(al + d, Al + srco);
            }
        } else {
            __half* AH = smh + buf * BUFF_H;
            __half* AL = AH + MAT_H;
            #pragma unroll
            for (int it = 0; it < 4; it++) {
                const int idx = tid + it * 256;
                const int row = idx >> 3;
                const int q   = idx & 7;
                const int k   = k0 + q * 4;
                float a0, a1, a2, a3;
                if (AK == 0) {
                    const float4 av = *(const float4*)(Af + (long)(bm0 + row) * Ka + k);
                    a0 = av.x; a1 = av.y; a2 = av.z; a3 = av.w;
                } else {
                    const int gm = bm0 + row;
                    const long arow = ((long)(gm >> 11) * Cz + chan) * Tz + (gm & (Tz - 1));
                    const float* ap = Af + arow * (long)Ka;
                    a0 = (k + 0 < Ka) ? ap[k + 0] : 0.f;
                    a1 = (k + 1 < Ka) ? ap[k + 1] : 0.f;
                    a2 = (k + 2 < Ka) ? ap[k + 2] : 0.f;
                    a3 = (k + 3 < Ka) ? ap[k + 3] : 0.f;
                }
                const __half h0 = __float2half_rn(a0), h1 = __float2half_rn(a1);
                const __half h2 = __float2half_rn(a2), h3 = __float2half_rn(a3);
                const __half l0 = __float2half_rn(a0 - __half2float(h0));
                const __half l1 = __float2half_rn(a1 - __half2float(h1));
                const __half l2 = __float2half_rn(a2 - __half2float(h2));
                const __half l3 = __float2half_rn(a3 - __half2float(h3));
                const int off = row * PITCH_H + q * 4;
                uint2 sh, sl;
                sh.x = pack2(h0, h1); sh.y = pack2(h2, h3);
                sl.x = pack2(l0, l1); sl.y = pack2(l2, l3);
                *(uint2*)(AH + off) = sh;
                *(uint2*)(AL + off) = sl;
            }
        }
    };
    auto loadB = [&](int kt, int buf){
        const int k0 = kt * 32;
        const uint32_t bh = smem_u32(smh + buf * BUFF_H + 2 * MAT_H);
        const uint32_t bl = bh + MAT_H * 2;
        #pragma unroll
        for (int it = 0; it < 2; it++) {
            const int idx = tid + it * 256;
            const int row = idx >> 2;
            const int c   = idx & 3;
            const uint32_t d = (uint32_t)((row * PITCH_H + c * 8) * 2);
            const long srco = (long)(n0 + row) * Kb + k0 + c * 8;
            CP_ASYNC16(bh + d, Bhi + srco);
            CP_ASYNC16(bl + d, Blo + srco);
        }
    };

    loadA(0, 0);
    loadB(0, 0);
    CP_COMMIT();

    for (int kt = 0; kt < Kt; kt++) {
        CP_WAIT0();
        __syncthreads();
        const int buf = kt & 1;
        if (kt + 1 < Kt) { loadA(kt + 1, buf ^ 1); loadB(kt + 1, buf ^ 1); CP_COMMIT(); }

        const uint32_t sb  = smem_u32(smh) + (uint32_t)buf * (BUFF_H * 2);
        const uint32_t AHb = sb;
        const uint32_t ALb = sb + MAT_H * 2;
        const uint32_t BHb = sb + 2 * (MAT_H * 2);
        const uint32_t BLb = sb + 3 * (MAT_H * 2);

        #pragma unroll
        for (int ks = 0; ks < 2; ks++) {
            const int kk = ks * 16;
            const uint32_t aoffb = (uint32_t)((a_off + kk) * 2);
            const uint32_t boffb = (uint32_t)((b_off + kk) * 2);

            uint32_t bh[2][4], bl[2][4];
            LDSM4(bh[0][0], bh[0][1], bh[0][2], bh[0][3], BHb + boffb);
            LDSM4(bh[1][0], bh[1][1], bh[1][2], bh[1][3], BHb + boffb + (uint32_t)(16 * PITCH_H * 2));
            LDSM4(bl[0][0], bl[0][1], bl[0][2], bl[0][3], BLb + boffb);
            LDSM4(bl[1][0], bl[1][1], bl[1][2], bl[1][3], BLb + boffb + (uint32_t)(16 * PITCH_H * 2));

            #pragma unroll
            for (int mp = 0; mp < 2; mp++) {
                uint32_t ah[2][4], al[2][4];
                const uint32_t a0s = aoffb + (uint32_t)((mp * 2) * 16 * PITCH_H * 2);
                const uint32_t a1s = a0s + (uint32_t)(16 * PITCH_H * 2);
                LDSM4(ah[0][0], ah[0][1], ah[0][2], ah[0][3], AHb + a0s);
                LDSM4(ah[1][0], ah[1][1], ah[1][2], ah[1][3], AHb + a1s);
                LDSM4(al[0][0], al[0][1], al[0][2], al[0][3], ALb + a0s);
                LDSM4(al[1][0], al[1][1], al[1][2], al[1][3], ALb + a1s);

                #pragma unroll
                for (int m2 = 0; m2 < 2; m2++)
                    #pragma unroll
                    for (int ntp = 0; ntp < 2; ntp++) {
                        float* d0 = acc[mp * 2 + m2][2 * ntp];
                        float* d1 = acc[mp * 2 + m2][2 * ntp + 1];
                        mma_f16(d0[0], d0[1], d0[2], d0[3],
                                ah[m2][0], ah[m2][1], ah[m2][2], ah[m2][3],
                                bh[ntp][0], bh[ntp][1]);
                        mma_f16(d1[0], d1[1], d1[2], d1[3],
                                ah[m2][0], ah[m2][1], ah[m2][2], ah[m2][3],
                                bh[ntp][2], bh[ntp][3]);
                    }
                #pragma unroll
                for (int m2 = 0; m2 < 2; m2++)
                    #pragma unroll
                    for (int ntp = 0; ntp < 2; ntp++) {
                        float* d0 = acc[mp * 2 + m2][2 * ntp];
                        float* d1 = acc[mp * 2 + m2][2 * ntp + 1];
                        mma_f16(d0[0], d0[1], d0[2], d0[3],
                                ah[m2][0], ah[m2][1], ah[m2][2], ah[m2][3],
                                bl[ntp][0], bl[ntp][1]);
                        mma_f16(d1[0], d1[1], d1[2], d1[3],
                                ah[m2][0], ah[m2][1], ah[m2][2], ah[m2][3],
                                bl[ntp][2], bl[ntp][3]);
                    }
                #pragma unroll
                for (int m2 = 0; m2 < 2; m2++)
                    #pragma unroll
                    for (int ntp = 0; ntp < 2; ntp++) {
                        float* d0 = acc[mp * 2 + m2][2 * ntp];
                        float* d1 = acc[mp * 2 + m2][2 * ntp + 1];
                        mma_f16(d0[0], d0[1], d0[2], d0[3],
                                al[m2][0], al[m2][1], al[m2][2], al[m2][3],
                                bh[ntp][0], bh[ntp][1]);
                        mma_f16(d1[0], d1[1], d1[2], d1[3],
                                al[m2][0], al[m2][1], al[m2][2], al[m2][3],
                                bh[ntp][2], bh[ntp][3]);
                    }
            }
        }
    }

    // epilogue
    const bool evenLd = ((ldD & 1) == 0);
    #pragma unroll
    for (int mt = 0; mt < 4; mt++) {
        #pragma unroll
        for (int nt = 0; nt < 4; nt++) {
            const int gn = n0 + wn * 32 + nt * 8 + 2 * t;
            if (gn >= N) continue;
            const float b0 = bias[gn];
            const float b1 = (gn + 1 < N) ? bias[gn + 1] : 0.f;
            #pragma unroll
            for (int h = 0; h < 2; h++) {
                const int gm = bm0 + wm * 64 + mt * 16 + g + h * 8;
                float v0 = acc[mt][nt][h * 2 + 0] + b0;
                float v1 = acc[mt][nt][h * 2 + 1] + b1;
                if (HAS_RES) {
                    const float* rp = Res + (long)gm * ldD + gn;
                    v0 += rp[0];
                    if (gn + 1 < N) v1 += rp[1];
                }
                if (RELU) { v0 = fmaxf(v0, 0.f); v1 = fmaxf(v1, 0.f); }
                if (QKV) {
                    float* dst;
                    if (gn < 256)      dst = Out0 + (long)gm * 256 + gn;
                    else if (gn < 512) dst = Out1 + ((long)chan * M2 + gm) * 256 + (gn - 256);
                    else               dst = Out2 + ((long)chan * M2 + gm) * 256 + (gn - 512);
                    *(float2*)dst = make_float2(v0, v1);
                } else {
                    if (OUT32) {
                        if (evenLd && gn + 1 < N) {
                            *(float2*)(Out0 + (long)gm * ldD + gn) = make_float2(v0, v1);
                        } else {
                            Out0[(long)gm * ldD + gn] = v0;
                            if (gn + 1 < N) Out0[(long)gm * ldD + gn + 1] = v1;
                        }
                    }
                    if (OUT16) {
                        const __half h0 = __float2half_rn(v0), h1 = __float2half_rn(v1);
                        const uint32_t ph = pack2(h0, h1);
                        const uint32_t pl = pack2(__float2half_rn(v0 - __half2float(h0)),
                                                  __float2half_rn(v1 - __half2float(h1)));
                        *(uint32_t*)(O16h + (long)gm * N + gn) = ph;
                        *(uint32_t*)(O16l + (long)gm * N + gn) = pl;
                    }
                }
            }
        }
    }
}

// ---------------- standalone GEMM wrapper ----------------
template<int AK, bool RELU, bool HAS_RES, bool QKV, bool OUT32, bool OUT16>
__global__ void __launch_bounds__(256, 2)
gemm_tc(const float* __restrict__ Af,
        const __half* __restrict__ Ah, const __half* __restrict__ Al,
        const __half* __restrict__ Bhi, const __half* __restrict__ Blo,
        const float* __restrict__ bias, const float* __restrict__ Res,
        float* __restrict__ Out0, float* __restrict__ Out1, float* __restrict__ Out2,
        __half* __restrict__ O16h, __half* __restrict__ O16l,
        int N, int ldD, int Ka, int Kb, int Kt, int chan, const float* gate)
{
    if (gate != nullptr && *gate < 0.5f) return;
    extern __shared__ __half smh[];
    gemm_dev<AK, RELU, HAS_RES, QKV, OUT32, OUT16>(
        Af, Ah, Al, Bhi, Blo, bias, Res, Out0, Out1, Out2, O16h, O16l,
        N, ldD, Ka, Kb, Kt, chan, blockIdx.y * 128, blockIdx.x * 128, smh);
}

// ---------------- channel attention: 2 rows/block (high occupancy) ----------------
__global__ void attn_kernel(const float* __restrict__ q, const float* __restrict__ k,
                            const float* __restrict__ v,
                            __half* __restrict__ ctxh, __half* __restrict__ ctxl,
                            int cc, const float* gate)
{
    if (*gate < 0.5f) return;
    const int wid = threadIdx.x >> 5;
    const int r = blockIdx.x * 2 + (wid >> 2);
    const int w = wid & 3;
    const int l = threadIdx.x & 31;
    const float* qp = q + (long)r * Hz + w * DHz;
    const float q0 = qp[l * 2], q1 = qp[l * 2 + 1];
    float sc[Cz];
    for (int c = 0; c < cc; c++) {
        const float* kp = k + ((long)c * M2 + r) * Hz + w * DHz;
        float p = q0 * kp[l * 2] + q1 * kp[l * 2 + 1];
        #pragma unroll
        for (int o = 16; o; o >>= 1) p += __shfl_xor_sync(0xffffffffu, p, o);
        sc[c] = p * 0.125f;
    }
    float mx = -1e30f;
    for (int c = 0; c < cc; c++) mx = fmaxf(mx, sc[c]);
    float se = 0.f;
    for (int c = 0; c < cc; c++) { sc[c] = expf(sc[c] - mx); se += sc[c]; }
    const float invs = 1.f / se;
    float o0 = 0.f, o1 = 0.f;
    for (int c = 0; c < cc; c++) {
        const float* vp = v + ((long)c * M2 + r) * Hz + w * DHz;
        const float a = sc[c] * invs;
        o0 += a * vp[l * 2]; o1 += a * vp[l * 2 + 1];
    }
    const long off = (long)r * Hz + w * DHz + l * 2;
    const __half h0 = __float2half_rn(o0), h1 = __float2half_rn(o1);
    *(uint32_t*)(ctxh + off) = pack2(h0, h1);
    *(uint32_t*)(ctxl + off) = pack2(__float2half_rn(o0 - __half2float(h0)),
                                     __float2half_rn(o1 - __half2float(h1)));
}

// ---------------- layernorm: one warp per row of 256 ----------------
__global__ void ln_kernel(const float* __restrict__ in, const float* __restrict__ g,
                          const float* __restrict__ b, float* __restrict__ out,
                          __half* __restrict__ oh, __half* __restrict__ ol,
                          const float* gate)
{
    if (*gate < 0.5f) return;
    const int r = blockIdx.x * 8 + (threadIdx.x >> 5);
    const int l = threadIdx.x & 31;
    const float* p = in + (long)r * Hz;
    float x[8]; float s = 0.f;
    #pragma unroll
    for (int j = 0; j < 8; j++) { x[j] = p[l + 32 * j]; s += x[j]; }
    #pragma unroll
    for (int o = 16; o; o >>= 1) s += __shfl_xor_sync(0xffffffffu, s, o);
    const float m = s * (1.f / 256.f);
    float vs = 0.f;
    #pragma unroll
    for (int j = 0; j < 8; j++) { const float d = x[j] - m; vs += d * d; }
    #pragma unroll
    for (int o = 16; o; o >>= 1) vs += __shfl_xor_sync(0xffffffffu, vs, o);
    const float inv = 1.f / sqrtf(vs * (1.f / 256.f) + 1e-5f);
    float* qo = out + (long)r * Hz;
    #pragma unroll
    for (int j = 0; j < 8; j++) {
        const int c = l + 32 * j;
        const float val = (x[j] - m) * inv * g[c] + b[c];
        qo[c] = val;
        const __half h = __float2half_rn(val);
        oh[(long)r * Hz + c] = h;
        ol[(long)r * Hz + c] = __float2half_rn(val - __half2float(h));
    }
}

// ---------------- ACT ponder update (standalone, gate update folded in) ----------------
__global__ void ponder_kernel(const float* __restrict__ s1, const float* __restrict__ Ws2,
                              const float* __restrict__ bs2, const float* __restrict__ ps_a,
                              const float* __restrict__ ps_b, const float* __restrict__ hh,
                              float* cum, float* rem, float* still, float* pc,
                              float* __restrict__ outacc,
                              int last, int first, float* gate, int* anyflag, int* done)
{
    if (*gate < 0.5f) return;
    const int wid  = threadIdx.x >> 5;
    const int lane = threadIdx.x & 31;
    const int r = blockIdx.x * 8 + wid;

    float p = 0.f;
    if (!last) {
        #pragma unroll
        for (int j = 0; j < 4; j++) {
            const int c = lane + 32 * j;
            p += s1[(long)r * HSz + c] * Ws2[c];
        }
    }
    #pragma unroll
    for (int o = 16; o; o >>= 1) p += __shfl_xor_sync(0xffffffffu, p, o);

    float wgt = 0.f;
    if (lane == 0) {
        float cur;
        if (last) cur = 1.f;
        else {
            const float s = p + bs2[0];
            const float z = (s - ps_a[0]) / (ps_b[0] + 1e-8f);
            cur = 1.f / (1.f + expf(-z));
        }
        const float cm = cum[r], st = still[r], rm = rem[r], p0 = pc[r];
        const float cum_n   = cm + cur * st;
        float pc_n          = p0 + st;
        const float still_n = (cum_n < 1.f - 1e-4f) ? 1.f : 0.f;
        const float rem_n   = rm - cur * still_n;
        pc_n += rem_n * (1.f - still_n);
        wgt = cur * still_n + rm * (1.f - still_n);
        cum[r] = cum_n; rem[r] = rem_n; still[r] = still_n; pc[r] = pc_n;
        if (still_n > 0.5f) *anyflag = 1;
    }
    wgt = __shfl_sync(0xffffffffu, wgt, 0);

    float4* oa = (float4*)(outacc + (long)r * Hz);
    const float4* hp = (const float4*)(hh + (long)r * Hz);
    #pragma unroll
    for (int j = 0; j < 2; j++) {
        const int i = lane * 2 + j;
        const float4 h4 = hp[i];
        if (first) {
            oa[i] = make_float4(h4.x * wgt, h4.y * wgt, h4.z * wgt, h4.w * wgt);
        } else {
            float4 o4 = oa[i];
            o4.x += h4.x * wgt; o4.y += h4.y * wgt;
            o4.z += h4.z * wgt; o4.w += h4.w * wgt;
            oa[i] = o4;
        }
    }

    __syncthreads();
    if (threadIdx.x == 0) {
        __threadfence();
        const int old = atomicAdd(done, 1);
        if (old == (int)gridDim.x - 1) {
            __threadfence();
            *gate = (*anyflag != 0) ? 1.f : 0.f;
            *anyflag = 0;
            *done = 0;
        }
    }
}

// ---------------- tail-kernel device phases (64 rows per CTA, grid 256) ----------------
__device__ void ln_dev(const float* __restrict__ in, const float* __restrict__ g,
                       const float* __restrict__ b, float* __restrict__ out,
                       __half* __restrict__ oh, __half* __restrict__ ol, int bx)
{
    const int wid = threadIdx.x >> 5;
    const int l = threadIdx.x & 31;
    #pragma unroll
    for (int j = 0; j < 8; j++) {
        const int r = bx * 64 + j * 8 + wid;
        const float* p = in + (long)r * Hz;
        float x[8]; float s = 0.f;
        #pragma unroll
        for (int q = 0; q < 8; q++) { x[q] = p[l + 32 * q]; s += x[q]; }
        #pragma unroll
        for (int o = 16; o; o >>= 1) s += __shfl_xor_sync(0xffffffffu, s, o);
        const float m = s * (1.f / 256.f);
        float vs = 0.f;
        #pragma unroll
        for (int q = 0; q < 8; q++) { const float d = x[q] - m; vs += d * d; }
        #pragma unroll
        for (int o = 16; o; o >>= 1) vs += __shfl_xor_sync(0xffffffffu, vs, o);
        const float inv = 1.f / sqrtf(vs * (1.f / 256.f) + 1e-5f);
        float* qo = out + (long)r * Hz;
        #pragma unroll
        for (int q = 0; q < 8; q++) {
            const int c = l + 32 * q;
            const float val = (x[q] - m) * inv * g[c] + b[c];
            qo[c] = val;
            const __half h = __float2half_rn(val);
            oh[(long)r * Hz + c] = h;
            ol[(long)r * Hz + c] = __float2half_rn(val - __half2float(h));
        }
    }
}

__device__ void attn_dev(const float* __restrict__ q, const float* __restrict__ k,
                         const float* __restrict__ v,
                         __half* __restrict__ ctxh, __half* __restrict__ ctxl,
                         int cc, int bx)
{
    const int wid = threadIdx.x >> 5;
    const int l = threadIdx.x & 31;
    for (int j = 0; j < 32; j++) {
        const int task = wid * 32 + j;
        const int rl = task >> 2, w = task & 3;
        const int r = bx * 64 + rl;
        const float* qp = q + (long)r * Hz + w * DHz;
        const float q0 = qp[l * 2], q1 = qp[l * 2 + 1];
        float sc[Cz];
        for (int c = 0; c < cc; c++) {
            const float* kp = k + ((long)c * M2 + r) * Hz + w * DHz;
            float p = q0 * kp[l * 2] + q1 * kp[l * 2 + 1];
            #pragma unroll
            for (int o = 16; o; o >>= 1) p += __shfl_xor_sync(0xffffffffu, p, o);
            sc[c] = p * 0.125f;
        }
        float mx = -1e30f;
        for (int c = 0; c < cc; c++) mx = fmaxf(mx, sc[c]);
        float se = 0.f;
        for (int c = 0; c < cc; c++) { sc[c] = expf(sc[c] - mx); se += sc[c]; }
        const float invs = 1.f / se;
        float o0 = 0.f, o1 = 0.f;
        for (int c = 0; c < cc; c++) {
            const float* vp = v + ((long)c * M2 + r) * Hz + w * DHz;
            const float a = sc[c] * invs;
            o0 += a * vp[l * 2]; o1 += a * vp[l * 2 + 1];
        }
        const long off = (long)r * Hz + w * DHz + l * 2;
        const __half h0 = __float2half_rn(o0), h1 = __float2half_rn(o1);
        *(uint32_t*)(ctxh + off) = pack2(h0, h1);
        *(uint32_t*)(ctxl + off) = pack2(__float2half_rn(o0 - __half2float(h0)),
                                         __float2half_rn(o1 - __half2float(h1)));
    }
}

__device__ void ponder_dev(const float* __restrict__ s1, const float* __restrict__ Ws2,
                           const float* __restrict__ bs2, const float* __restrict__ ps_a,
                           const float* __restrict__ ps_b, const float* __restrict__ hh,
                           int last, int chan, int bx)
{
    const int wid  = threadIdx.x >> 5;
    const int lane = threadIdx.x & 31;
    #pragma unroll
    for (int j = 0; j < 8; j++) {
        const int r = bx * 64 + j * 8 + wid;
        float p = 0.f;
        if (!last) {
            #pragma unroll
            for (int q = 0; q < 4; q++) {
                const int c = lane + 32 * q;
                p += s1[(long)r * HSz + c] * Ws2[c];
            }
        }
        #pragma unroll
        for (int o = 16; o; o >>= 1) p += __shfl_xor_sync(0xffffffffu, p, o);

        float wgt = 0.f;
        if (lane == 0) {
            float cur;
            if (last) cur = 1.f;
            else {
                const float s = p + bs2[0];
                const float z = (s - ps_a[0]) / (ps_b[0] + 1e-8f);
                cur = 1.f / (1.f + expf(-z));
            }
            const float cm = g_cum[r], st = g_still[r], rm = g_rem[r], p0 = g_pc[r];
            const float cum_n   = cm + cur * st;
            float pc_n          = p0 + st;
            const float still_n = (cum_n < 1.f - 1e-4f) ? 1.f : 0.f;
            const float rem_n   = rm - cur * still_n;
            pc_n += rem_n * (1.f - still_n);
            wgt = cur * still_n + rm * (1.f - still_n);
            g_cum[r] = cum_n; g_rem[r] = rem_n; g_still[r] = still_n; g_pc[r] = pc_n;
            if (still_n > 0.5f) g_any2[chan] = 1;
        }
        wgt = __shfl_sync(0xffffffffu, wgt, 0);

        float4* oa = (float4*)(g_outacc + (long)r * Hz);
        const float4* hp = (const float4*)(hh + (long)r * Hz);
        #pragma unroll
        for (int q = 0; q < 2; q++) {
            const int i = lane * 2 + q;
            const float4 h4 = hp[i];
            float4 o4 = oa[i];
            o4.x += h4.x * wgt; o4.y += h4.y * wgt;
            o4.z += h4.z * wgt; o4.w += h4.w * wgt;
            oa[i] = o4;
        }
    }
}

// ---------------- persistent tail: iterations 3..7, one launch ----------------
__global__ void __launch_bounds__(256, 2)
tail_kernel(const float* __restrict__ x, const float* __restrict__ b_in,
            const float* __restrict__ bo,
            const float* __restrict__ ln1_g, const float* __restrict__ ln1_b,
            const float* __restrict__ bf1, const float* __restrict__ bf2,
            const float* __restrict__ ln2_g, const float* __restrict__ ln2_b,
            const float* __restrict__ bs1, const float* __restrict__ Ws2,
            const float* __restrict__ bs2, const float* __restrict__ ps_a,
            const float* __restrict__ ps_b)
{
    if (g_gate[0] < 0.5f) return;     // expected path: gate died at iteration 2
    extern __shared__ __half smh[];
    const int bx = blockIdx.x;

    for (int chan = 3; chan < Cz; chan++) {
        const int last = (chan == Cz - 1) ? 1 : 0;
        const int base = (chan - 3) * 10;

        gemm_dev<1, true, false, false, true, true>(
            x, nullptr, nullptr, g_bt_in_hi, g_bt_in_lo, b_in, nullptr,
            g_lin1, nullptr, nullptr, g_lin1_h, g_lin1_l,
            256, 256, 257, 288, 9, chan, (bx >> 1) * 128, (bx & 1) * 128, smh);
        __syncthreads();
        grid_bar2(base + 0);

        for (int s = 0; s < 3; s++) {
            const int id = bx + 256 * s;
            gemm_dev<2, false, false, true, true, false>(
                nullptr, g_lin1_h, g_lin1_l, g_bt_qkv_hi, g_bt_qkv_lo, g_bqkv, nullptr,
                g_q, g_k, g_v, nullptr, nullptr,
                768, 768, 256, 256, 8, chan, (id / 6) * 128, (id % 6) * 128, smh);
            __syncthreads();
        }
        grid_bar2(base + 1);

        attn_dev(g_q, g_k, g_v, g_ctx_h, g_ctx_l, chan + 1, bx);
        grid_bar2(base + 2);

        gemm_dev<2, false, true, false, true, false>(
            nullptr, g_ctx_h, g_ctx_l, g_bt_o_hi, g_bt_o_lo, bo, g_lin1,
            g_h1pre, nullptr, nullptr, nullptr, nullptr,
            256, 256, 256, 256, 8, 0, (bx >> 1) * 128, (bx & 1) * 128, smh);
        __syncthreads();
        grid_bar2(base + 3);

        ln_dev(g_h1pre, ln1_g, ln1_b, g_h1, g_h1_h, g_h1_l, bx);
        grid_bar2(base + 4);

        for (int s = 0; s < 2; s++) {
            const int id = bx + 256 * s;
            gemm_dev<2, true, false, false, false, true>(
                nullptr, g_h1_h, g_h1_l, g_bt_f1_hi, g_bt_f1_lo, bf1, nullptr,
                nullptr, nullptr, nullptr, g_f1_h, g_f1_l,
                512, 512, 256, 256, 8, 0, (id / 4) * 128, (id % 4) * 128, smh);
            __syncthreads();
        }
        grid_bar2(base + 5);

        gemm_dev<2, false, true, false, true, false>(
            nullptr, g_f1_h, g_f1_l, g_bt_f2_hi, g_bt_f2_lo, bf2, g_h1,
            g_hhpre, nullptr, nullptr, nullptr, nullptr,
            256, 256, 512, 512, 16, 0, (bx >> 1) * 128, (bx & 1) * 128, smh);
        __syncthreads();
        grid_bar2(base + 6);

        ln_dev(g_hhpre, ln2_g, ln2_b, g_hh, g_hh_h, g_hh_l, bx);
        grid_bar2(base + 7);

        if (!last && bx < 128) {
            gemm_dev<2, true, false, false, true, false>(
                nullptr, g_hh_h, g_hh_l, g_bt_s1_hi, g_bt_s1_lo, bs1, nullptr,
                g_s1, nullptr, nullptr, nullptr, nullptr,
                128, 128, 256, 256, 8, 0, bx * 128, 0, smh);
            __syncthreads();
        }
        grid_bar2(base + 8);

        ponder_dev(g_s1, Ws2, bs2, ps_a, ps_b, g_hh, last, chan, bx);
        grid_bar2(base + 9);

        if (g_any2[chan] == 0) break;   // all rows halted: stop (race-free: set before barrier)
    }
}

// ---------------- one-shot prep ----------------
__global__ void prep_kernel(const float* __restrict__ W_in, const float* __restrict__ Wq,
                            const float* __restrict__ Wk, const float* __restrict__ Wv,
                            const float* __restrict__ Wo, const float* __restrict__ Wf1,
                            const float* __restrict__ Wf2, const float* __restrict__ Ws1,
                            const float* __restrict__ W_out,
                            const float* __restrict__ bq, const float* __restrict__ bk,
                            const float* __restrict__ bv)
{
    const int i = blockIdx.x * 256 + threadIdx.x;
    float v; int li;
    __half *dh, *dl;
    if (i < 73728) {            // W_in: K=257 N=256 Kpad=288
        li = i; const int n = li / 288, k = li % 288;
        v = (k < 257) ? W_in[(long)k * 256 + n] : 0.f;
        dh = g_bt_in_hi; dl = g_bt_in_lo;
    } else if (i < 139264) {    // Wq
        li = i - 73728; const int n = li / 256, k = li % 256;
        v = Wq[(long)k * 256 + n];
        dh = g_bt_qkv_hi; dl = g_bt_qkv_lo;
    } else if (i < 204800) {    // Wk
        li = i - 139264; const int n = li / 256, k = li % 256;
        v = Wk[(long)k * 256 + n];
        dh = g_bt_qkv_hi + 65536; dl = g_bt_qkv_lo + 65536;
    } else if (i < 270336) {    // Wv
        li = i - 204800; const int n = li / 256, k = li % 256;
        v = Wv[(long)k * 256 + n];
        dh = g_bt_qkv_hi + 131072; dl = g_bt_qkv_lo + 131072;
    } else if (i < 335872) {    // Wo
        li = i - 270336; const int n = li / 256, k = li % 256;
        v = Wo[(long)k * 256 + n];
        dh = g_bt_o_hi; dl = g_bt_o_lo;
    } else if (i < 466944) {    // Wf1: K=256 N=512
        li = i - 335872; const int n = li / 256, k = li % 256;
        v = Wf1[(long)k * 512 + n];
        dh = g_bt_f1_hi; dl = g_bt_f1_lo;
    } else if (i < 598016) {    // Wf2: K=512 N=256
        li = i - 466944; const int n = li / 512, k = li % 512;
        v = Wf2[(long)k * 256 + n];
        dh = g_bt_f2_hi; dl = g_bt_f2_lo;
    } else if (i < 630784) {    // Ws1: K=256 N=128
        li = i - 598016; const int n = li / 256, k = li % 256;
        v = Ws1[(long)k * 128 + n];
        dh = g_bt_s1_hi; dl = g_bt_s1_lo;
    } else if (i < 696320) {    // W_out cols 0..255
        li = i - 630784; const int n = li / 256, k = li % 256;
        v = W_out[(long)k * 257 + n];
        dh = g_bt_out_hi; dl = g_bt_out_lo;
    } else if (i < 697088) {    // bqkv
        const int j = i - 696320;
        g_bqkv[j] = (j < 256) ? bq[j] : ((j < 512) ? bk[j - 256] : bv[j - 512]);
        return;
    } else if (i < 713472) {    // per-row ACT state + flags
        const int r = i - 697088;
        g_cum[r] = 0.f; g_rem[r] = 1.f; g_still[r] = 1.f; g_pc[r] = 0.f;
        if (r < 64) g_bar2[r] = 0;
        if (r < 8)  g_any2[r] = 0;
        if (r == 0) { g_gate[0] = 1.f; g_any[0] = 0; g_done[0] = 0; }
        return;
    } else return;
    const __half h = __float2half_rn(v);
    dh[li] = h;
    dl[li] = __float2half_rn(v - __half2float(h));
}

// ---------------- final column 256 GEMV + pc writeout ----------------
__global__ void gemv_pc_kernel(float* __restrict__ out, const float* __restrict__ outacc,
                               const float* __restrict__ W_out, const float* __restrict__ b_out,
                               const float* __restrict__ pc)
{
    __shared__ float wc[256];
    const int tid = threadIdx.x;
    wc[tid] = W_out[(long)tid * 257 + 256];
    __syncthreads();
    const float bb = b_out[256];
    const int wid = tid >> 5, lane = tid & 31;

    for (int j = 0; j < 32; j++) {
        const int r = blockIdx.x * 256 + j * 8 + wid;
        const float4* ap = (const float4*)(outacc + (long)r * Hz);
        float dot = 0.f;
        #pragma unroll
        for (int q = 0; q < 2; q++) {
            const int base = lane * 8 + q * 4;
            const float4 a4 = ap[lane * 2 + q];
            dot += a4.x * wc[base] + a4.y * wc[base + 1] + a4.z * wc[base + 2] + a4.w * wc[base + 3];
        }
        #pragma unroll
        for (int o = 16; o; o >>= 1) dot += __shfl_xor_sync(0xffffffffu, dot, o);
        if (lane == 0) out[(long)r * 257 + 256] = fmaxf(dot + bb, 0.f);
    }
    const int r = blockIdx.x * 256 + tid;
    out[BTF + r] = pc[r];
}

// ---------------- host launch ----------------
static void* symA(const void* s)
{
    void* p = nullptr;
    cudaGetSymbolAddress(&p, s);
    return p;
}

extern "C" void kernel_launch(void* const* d_in, const int* in_sizes, int n_in,
                              void* d_out, int out_size)
{
    const float* x     = (const float*)d_in[0];
    const float* W_in  = (const float*)d_in[1];
    const float* b_in  = (const float*)d_in[2];
    const float* W_out = (const float*)d_in[3];
    const float* b_out = (const float*)d_in[4];
    const float* Wq    = (const float*)d_in[5];
    const float* bq    = (const float*)d_in[6];
    const float* Wk    = (const float*)d_in[7];
    const float* bk    = (const float*)d_in[8];
    const float* Wv    = (const float*)d_in[9];
    const float* bv    = (const float*)d_in[10];
    const float* Wo    = (const float*)d_in[11];
    const float* bo    = (const float*)d_in[12];
    const float* ln1_g = (const float*)d_in[13];
    const float* ln1_b = (const float*)d_in[14];
    const float* Wf1   = (const float*)d_in[15];
    const float* bf1   = (const float*)d_in[16];
    const float* Wf2   = (const float*)d_in[17];
    const float* bf2   = (const float*)d_in[18];
    const float* ln2_g = (const float*)d_in[19];
    const float* ln2_b = (const float*)d_in[20];
    const float* Ws1   = (const float*)d_in[21];
    const float* bs1   = (const float*)d_in[22];
    const float* Ws2   = (const float*)d_in[23];
    const float* bs2   = (const float*)d_in[24];
    const float* ps_a  = (const float*)d_in[25];
    const float* ps_b  = (const float*)d_in[26];
    float* out = (float*)d_out;

    float* p_lin1  = (float*)symA(g_lin1);
    float* p_q     = (float*)symA(g_q);
    float* p_k     = (float*)symA(g_k);
    float* p_v     = (float*)symA(g_v);
    float* p_h1pre = (float*)symA(g_h1pre);
    float* p_h1    = (float*)symA(g_h1);
    float* p_hhpre = (float*)symA(g_hhpre);
    float* p_hh    = (float*)symA(g_hh);
    float* p_s1    = (float*)symA(g_s1);
    float* p_oacc  = (float*)symA(g_outacc);
    float* p_cum   = (float*)symA(g_cum);
    float* p_rem   = (float*)symA(g_rem);
    float* p_still = (float*)symA(g_still);
    float* p_pc    = (float*)symA(g_pc);
    float* p_bqkv  = (float*)symA(g_bqkv);
    float* p_gate  = (float*)symA(g_gate);
    int*   p_any   = (int*)symA(g_any);
    int*   p_done  = (int*)symA(g_done);

    __half* lin1_h = (__half*)symA(g_lin1_h), *lin1_l = (__half*)symA(g_lin1_l);
    __half* ctx_h  = (__half*)symA(g_ctx_h),  *ctx_l  = (__half*)symA(g_ctx_l);
    __half* h1_h   = (__half*)symA(g_h1_h),   *h1_l   = (__half*)symA(g_h1_l);
    __half* f1a_h  = (__half*)symA(g_f1_h),   *f1a_l  = (__half*)symA(g_f1_l);
    __half* hh_h   = (__half*)symA(g_hh_h),   *hh_l   = (__half*)symA(g_hh_l);

    __half* bt_in_h  = (__half*)symA(g_bt_in_hi),  *bt_in_l  = (__half*)symA(g_bt_in_lo);
    __half* bt_qkv_h = (__half*)symA(g_bt_qkv_hi), *bt_qkv_l = (__half*)symA(g_bt_qkv_lo);
    __half* bt_o_h   = (__half*)symA(g_bt_o_hi),   *bt_o_l   = (__half*)symA(g_bt_o_lo);
    __half* bt_f1_h  = (__half*)symA(g_bt_f1_hi),  *bt_f1_l  = (__half*)symA(g_bt_f1_lo);
    __half* bt_f2_h  = (__half*)symA(g_bt_f2_hi),  *bt_f2_l  = (__half*)symA(g_bt_f2_lo);
    __half* bt_s1_h  = (__half*)symA(g_bt_s1_hi),  *bt_s1_l  = (__half*)symA(g_bt_s1_lo);
    __half* bt_out_h = (__half*)symA(g_bt_out_hi), *bt_out_l = (__half*)symA(g_bt_out_lo);

    cudaFuncSetAttribute((const void*)gemm_tc<1, true,  false, false, true,  true >,
                         cudaFuncAttributeMaxDynamicSharedMemorySize, SMEM_DYN);
    cudaFuncSetAttribute((const void*)gemm_tc<2, false, false, true,  true,  false>,
                         cudaFuncAttributeMaxDynamicSharedMemorySize, SMEM_DYN);
    cudaFuncSetAttribute((const void*)gemm_tc<2, false, true,  false, true,  false>,
                         cudaFuncAttributeMaxDynamicSharedMemorySize, SMEM_DYN);
    cudaFuncSetAttribute((const void*)gemm_tc<2, true,  false, false, false, true >,
                         cudaFuncAttributeMaxDynamicSharedMemorySize, SMEM_DYN);
    cudaFuncSetAttribute((const void*)gemm_tc<2, true,  false, false, true,  false>,
                         cudaFuncAttributeMaxDynamicSharedMemorySize, SMEM_DYN);
    cudaFuncSetAttribute((const void*)gemm_tc<0, true,  false, false, true,  false>,
                         cudaFuncAttributeMaxDynamicSharedMemorySize, SMEM_DYN);
    cudaFuncSetAttribute((const void*)tail_kernel,
                         cudaFuncAttributeMaxDynamicSharedMemorySize, SMEM_DYN);

    // one-shot prep
    prep_kernel<<<2788, 256>>>(W_in, Wq, Wk, Wv, Wo, Wf1, Wf2, Ws1, W_out, bq, bk, bv);

    // iterations 0..2: separate high-occupancy kernels (expected live)
    for (int ci = 0; ci < 3; ci++) {
        gemm_tc<1, true, false, false, true, true><<<dim3(2, 128), 256, SMEM_DYN>>>(
            x, nullptr, nullptr, bt_in_h, bt_in_l, b_in, nullptr,
            p_lin1, nullptr, nullptr, lin1_h, lin1_l,
            256, 256, 257, 288, 9, ci, p_gate);
        gemm_tc<2, false, false, true, true, false><<<dim3(6, 128), 256, SMEM_DYN>>>(
            nullptr, lin1_h, lin1_l, bt_qkv_h, bt_qkv_l, p_bqkv, nullptr,
            p_q, p_k, p_v, nullptr, nullptr,
            768, 768, 256, 256, 8, ci, p_gate);
        attn_kernel<<<8192, 256>>>(p_q, p_k, p_v, ctx_h, ctx_l, ci + 1, p_gate);
        gemm_tc<2, false, true, false, true, false><<<dim3(2, 128), 256, SMEM_DYN>>>(
            nullptr, ctx_h, ctx_l, bt_o_h, bt_o_l, bo, p_lin1,
            p_h1pre, nullptr, nullptr, nullptr, nullptr,
            256, 256, 256, 256, 8, 0, p_gate);
        ln_kernel<<<2048, 256>>>(p_h1pre, ln1_g, ln1_b, p_h1, h1_h, h1_l, p_gate);
        gemm_tc<2, true, false, false, false, true><<<dim3(4, 128), 256, SMEM_DYN>>>(
            nullptr, h1_h, h1_l, bt_f1_h, bt_f1_l, bf1, nullptr,
            nullptr, nullptr, nullptr, f1a_h, f1a_l,
            512, 512, 256, 256, 8, 0, p_gate);
        gemm_tc<2, false, true, false, true, false><<<dim3(2, 128), 256, SMEM_DYN>>>(
            nullptr, f1a_h, f1a_l, bt_f2_h, bt_f2_l, bf2, p_h1,
            p_hhpre, nullptr, nullptr, nullptr, nullptr,
            256, 256, 512, 512, 16, 0, p_gate);
        ln_kernel<<<2048, 256>>>(p_hhpre, ln2_g, ln2_b, p_hh, hh_h, hh_l, p_gate);
        gemm_tc<2, true, false, false, true, false><<<dim3(1, 128), 256, SMEM_DYN>>>(
            nullptr, hh_h, hh_l, bt_s1_h, bt_s1_l, bs1, nullptr,
            p_s1, nullptr, nullptr, nullptr, nullptr,
            128, 128, 256, 256, 8, 0, p_gate);
        ponder_kernel<<<2048, 256>>>(p_s1, Ws2, bs2, ps_a, ps_b, p_hh,
                                     p_cum, p_rem, p_still, p_pc, p_oacc,
                                     0, (ci == 0) ? 1 : 0,
                                     p_gate, p_any, p_done);
    }

    // iterations 3..7: single persistent tail launch (early-exits if gate dead)
    tail_kernel<<<256, 256, SMEM_DYN>>>(
        x, b_in, bo, ln1_g, ln1_b, bf1, bf2, ln2_g, ln2_b,
        bs1, Ws2, bs2, ps_a, ps_b);

    // encoder_out cols 0..255 (ldD = 257)
    gemm_tc<0, true, false, false, true, false><<<dim3(2, 128), 256, SMEM_DYN>>>(
        p_oacc, nullptr, nullptr, bt_out_h, bt_out_l, b_out, nullptr,
        out, nullptr, nullptr, nullptr, nullptr,
        256, 257, 256, 256, 8, 0, nullptr);
    // col 256 GEMV + pc writeout
    gemv_pc_kernel<<<64, 256>>>(out, p_oacc, W_out, b_out, p_pc);
}

// round 17
// speedup vs baseline: 1.0022x; 1.0022x over previous
#include <cuda_runtime.h>
#include <cuda_fp16.h>
#include <math.h>
#include <stdint.h>

// ---------------- problem constants ----------------
#define Bz   8
#define Cz   8
#define Tz   2048
#define Fz   257
#define Hz   256
#define NHz  4
#define DHz  64
#define WINz 512
#define HSz  128
#define M2   (Bz*Tz)        // 16384 rows
#define BTF  (M2*Fz)

// ---------------- device scratch ----------------
__device__ __align__(16) float g_lin1 [M2*Hz];
__device__ __align__(16) float g_q    [M2*Hz];
__device__ __align__(16) float g_k    [Cz*M2*Hz];
__device__ __align__(16) float g_v    [Cz*M2*Hz];
__device__ __align__(16) float g_h1pre[M2*Hz];
__device__ __align__(16) float g_h1   [M2*Hz];
__device__ __align__(16) float g_hhpre[M2*Hz];
__device__ __align__(16) float g_hh   [M2*Hz];
__device__ __align__(16) float g_s1   [M2*HSz];
__device__ __align__(16) float g_outacc[M2*Hz];
__device__ float g_cum[M2], g_rem[M2], g_still[M2], g_pc[M2];
__device__ __align__(16) float g_bqkv[768];
__device__ float g_gate[1];
__device__ int   g_any[1];
__device__ int   g_done[1];
__device__ int   g_any2[8];     // per-iteration alive flags (tail kernel)
__device__ int   g_bar2[64];    // grid-barrier counters for tail kernel

// fp16 hi/lo activation copies (GEMM A operands)
__device__ __align__(16) __half g_lin1_h[M2*Hz], g_lin1_l[M2*Hz];
__device__ __align__(16) __half g_ctx_h [M2*Hz], g_ctx_l [M2*Hz];
__device__ __align__(16) __half g_h1_h  [M2*Hz], g_h1_l  [M2*Hz];
__device__ __align__(16) __half g_f1_h  [M2*WINz], g_f1_l[M2*WINz];
__device__ __align__(16) __half g_hh_h  [M2*Hz], g_hh_l  [M2*Hz];

// transposed + fp16-split weights: Bt[n][k], zero padded
__device__ __align__(16) __half g_bt_in_hi [256*288],  g_bt_in_lo [256*288];
__device__ __align__(16) __half g_bt_qkv_hi[768*256],  g_bt_qkv_lo[768*256];
__device__ __align__(16) __half g_bt_o_hi  [256*256],  g_bt_o_lo  [256*256];
__device__ __align__(16) __half g_bt_f1_hi [512*256],  g_bt_f1_lo [512*256];
__device__ __align__(16) __half g_bt_f2_hi [256*512],  g_bt_f2_lo [256*512];
__device__ __align__(16) __half g_bt_s1_hi [128*256],  g_bt_s1_lo [128*256];
__device__ __align__(16) __half g_bt_out_hi[256*256],  g_bt_out_lo[256*256];  // cols 0..255

// ---------------- helpers ----------------
__device__ __forceinline__ uint32_t smem_u32(const void* p){
    uint32_t a;
    asm("{ .reg .u64 t; cvta.to.shared.u64 t, %1; cvt.u32.u64 %0, t; }" : "=r"(a) : "l"(p));
    return a;
}
#define CP_ASYNC16(dst, src) asm volatile("cp.async.ca.shared.global [%0], [%1], 16;" :: "r"(dst), "l"(src))
#define CP_COMMIT() asm volatile("cp.async.commit_group;" ::: "memory")
#define CP_WAIT0()  asm volatile("cp.async.wait_group 0;" ::: "memory")

#define LDSM4(r0,r1,r2,r3,addr) asm volatile( \
    "ldmatrix.sync.aligned.m8n8.x4.shared.b16 {%0,%1,%2,%3}, [%4];" \
    : "=r"(r0),"=r"(r1),"=r"(r2),"=r"(r3) : "r"(addr))

__device__ __forceinline__ void mma_f16(float& d0, float& d1, float& d2, float& d3,
                                        uint32_t a0, uint32_t a1, uint32_t a2, uint32_t a3,
                                        uint32_t b0, uint32_t b1){
    asm volatile("mma.sync.aligned.m16n8k16.row.col.f32.f16.f16.f32 "
        "{%0,%1,%2,%3}, {%4,%5,%6,%7}, {%8,%9}, {%0,%1,%2,%3};"
        : "+f"(d0), "+f"(d1), "+f"(d2), "+f"(d3)
        : "r"(a0), "r"(a1), "r"(a2), "r"(a3), "r"(b0), "r"(b1));
}
__device__ __forceinline__ uint32_t pack2(__half x, __half y){
    __half2 h = __halves2half2(x, y);
    return *(uint32_t*)&h;
}

// grid-wide barrier for the tail kernel (all 256 CTAs co-resident at 2 CTA/SM)
__device__ __forceinline__ void grid_bar2(int slot){
    __syncthreads();
    if (threadIdx.x == 0){
        __threadfence();
        atomicAdd(&g_bar2[slot], 1);
        while (*(volatile int*)&g_bar2[slot] < (int)gridDim.x) { }
        __threadfence();
    }
    __syncthreads();
}

// ---------------- GEMM core (device fn, 3xFP16 split, term-major ILP) ----------------
#define PITCH_H 40
#define MAT_H   (128*PITCH_H)
#define BUFF_H  (4*MAT_H)
#define SMEM_DYN (2*BUFF_H*2)    // 81920 bytes

template<int AK, bool RELU, bool HAS_RES, bool QKV, bool OUT32, bool OUT16>
__device__ void gemm_dev(const float* __restrict__ Af,
        const __half* __restrict__ Ah, const __half* __restrict__ Al,
        const __half* __restrict__ Bhi, const __half* __restrict__ Blo,
        const float* __restrict__ bias, const float* __restrict__ Res,
        float* __restrict__ Out0, float* __restrict__ Out1, float* __restrict__ Out2,
        __half* __restrict__ O16h, __half* __restrict__ O16l,
        int N, int ldD, int Ka, int Kb, int Kt, int chan, int bm0, int n0, __half* smh)
{
    const int tid  = threadIdx.x;
    const int wid  = tid >> 5;
    const int lane = tid & 31;
    const int g    = lane >> 2;
    const int t    = lane & 3;
    const int lq   = lane & 7;
    const int quad = lane >> 3;
    const int wm   = wid & 1;
    const int wn   = wid >> 1;

    const int a_off = (wm * 64 + lq + (quad & 1) * 8) * PITCH_H + (quad >> 1) * 8;
    const int b_off = (wn * 32 + (quad >> 1) * 8 + lq) * PITCH_H + (quad & 1) * 8;

    float acc[4][4][4];
    #pragma unroll
    for (int i = 0; i < 4; i++)
        #pragma unroll
        for (int j = 0; j < 4; j++)
            #pragma unroll
            for (int r = 0; r < 4; r++) acc[i][j][r] = 0.f;

    auto loadA = [&](int kt, int buf){
        const int k0 = kt * 32;
        if (AK == 2) {
            const uint32_t ah = smem_u32(smh + buf * BUFF_H);
            const uint32_t al = ah + MAT_H * 2;
            #pragma unroll
            for (int it = 0; it < 2; it++) {
                const int idx = tid + it * 256;
                const int row = idx >> 2;
                const int c   = idx & 3;
                const uint32_t d = (uint32_t)((row * PITCH_H + c * 8) * 2);
                const long srco = (long)(bm0 + row) * Ka + k0 + c * 8;
                CP_ASYNC16(ah + d, Ah + srco);
                CP_ASYNC16(al + d, Al + srco);
            }
        } else {
            __half* AH = smh + buf * BUFF_H;
            __half* AL = AH + MAT_H;
            #pragma unroll
            for (int it = 0; it < 4; it++) {
                const int idx = tid + it * 256;
                const int row = idx >> 3;
                const int q   = idx & 7;
                const int k   = k0 + q * 4;
                float a0, a1, a2, a3;
                if (AK == 0) {
                    const float4 av = *(const float4*)(Af + (long)(bm0 + row) * Ka + k);
                    a0 = av.x; a1 = av.y; a2 = av.z; a3 = av.w;
                } else {
                    const int gm = bm0 + row;
                    const long arow = ((long)(gm >> 11) * Cz + chan) * Tz + (gm & (Tz - 1));
                    const float* ap = Af + arow * (long)Ka;
                    a0 = (k + 0 < Ka) ? ap[k + 0] : 0.f;
                    a1 = (k + 1 < Ka) ? ap[k + 1] : 0.f;
                    a2 = (k + 2 < Ka) ? ap[k + 2] : 0.f;
                    a3 = (k + 3 < Ka) ? ap[k + 3] : 0.f;
                }
                const __half h0 = __float2half_rn(a0), h1 = __float2half_rn(a1);
                const __half h2 = __float2half_rn(a2), h3 = __float2half_rn(a3);
                const __half l0 = __float2half_rn(a0 - __half2float(h0));
                const __half l1 = __float2half_rn(a1 - __half2float(h1));
                const __half l2 = __float2half_rn(a2 - __half2float(h2));
                const __half l3 = __float2half_rn(a3 - __half2float(h3));
                const int off = row * PITCH_H + q * 4;
                uint2 sh, sl;
                sh.x = pack2(h0, h1); sh.y = pack2(h2, h3);
                sl.x = pack2(l0, l1); sl.y = pack2(l2, l3);
                *(uint2*)(AH + off) = sh;
                *(uint2*)(AL + off) = sl;
            }
        }
    };
    auto loadB = [&](int kt, int buf){
        const int k0 = kt * 32;
        const uint32_t bh = smem_u32(smh + buf * BUFF_H + 2 * MAT_H);
        const uint32_t bl = bh + MAT_H * 2;
        #pragma unroll
        for (int it = 0; it < 2; it++) {
            const int idx = tid + it * 256;
            const int row = idx >> 2;
            const int c   = idx & 3;
            const uint32_t d = (uint32_t)((row * PITCH_H + c * 8) * 2);
            const long srco = (long)(n0 + row) * Kb + k0 + c * 8;
            CP_ASYNC16(bh + d, Bhi + srco);
            CP_ASYNC16(bl + d, Blo + srco);
        }
    };

    loadA(0, 0);
    loadB(0, 0);
    CP_COMMIT();

    for (int kt = 0; kt < Kt; kt++) {
        CP_WAIT0();
        __syncthreads();
        const int buf = kt & 1;
        if (kt + 1 < Kt) { loadA(kt + 1, buf ^ 1); loadB(kt + 1, buf ^ 1); CP_COMMIT(); }

        const uint32_t sb  = smem_u32(smh) + (uint32_t)buf * (BUFF_H * 2);
        const uint32_t AHb = sb;
        const uint32_t ALb = sb + MAT_H * 2;
        const uint32_t BHb = sb + 2 * (MAT_H * 2);
        const uint32_t BLb = sb + 3 * (MAT_H * 2);

        #pragma unroll
        for (int ks = 0; ks < 2; ks++) {
            const int kk = ks * 16;
            const uint32_t aoffb = (uint32_t)((a_off + kk) * 2);
            const uint32_t boffb = (uint32_t)((b_off + kk) * 2);

            uint32_t bh[2][4], bl[2][4];
            LDSM4(bh[0][0], bh[0][1], bh[0][2], bh[0][3], BHb + boffb);
            LDSM4(bh[1][0], bh[1][1], bh[1][2], bh[1][3], BHb + boffb + (uint32_t)(16 * PITCH_H * 2));
            LDSM4(bl[0][0], bl[0][1], bl[0][2], bl[0][3], BLb + boffb);
            LDSM4(bl[1][0], bl[1][1], bl[1][2], bl[1][3], BLb + boffb + (uint32_t)(16 * PITCH_H * 2));

            #pragma unroll
            for (int mp = 0; mp < 2; mp++) {
                uint32_t ah[2][4], al[2][4];
                const uint32_t a0s = aoffb + (uint32_t)((mp * 2) * 16 * PITCH_H * 2);
                const uint32_t a1s = a0s + (uint32_t)(16 * PITCH_H * 2);
                LDSM4(ah[0][0], ah[0][1], ah[0][2], ah[0][3], AHb + a0s);
                LDSM4(ah[1][0], ah[1][1], ah[1][2], ah[1][3], AHb + a1s);
                LDSM4(al[0][0], al[0][1], al[0][2], al[0][3], ALb + a0s);
                LDSM4(al[1][0], al[1][1], al[1][2], al[1][3], ALb + a1s);

                #pragma unroll
                for (int m2 = 0; m2 < 2; m2++)
                    #pragma unroll
                    for (int ntp = 0; ntp < 2; ntp++) {
                        float* d0 = acc[mp * 2 + m2][2 * ntp];
                        float* d1 = acc[mp * 2 + m2][2 * ntp + 1];
                        mma_f16(d0[0], d0[1], d0[2], d0[3],
                                ah[m2][0], ah[m2][1], ah[m2][2], ah[m2][3],
                                bh[ntp][0], bh[ntp][1]);
                        mma_f16(d1[0], d1[1], d1[2], d1[3],
                                ah[m2][0], ah[m2][1], ah[m2][2], ah[m2][3],
                                bh[ntp][2], bh[ntp][3]);
                    }
                #pragma unroll
                for (int m2 = 0; m2 < 2; m2++)
                    #pragma unroll
                    for (int ntp = 0; ntp < 2; ntp++) {
                        float* d0 = acc[mp * 2 + m2][2 * ntp];
                        float* d1 = acc[mp * 2 + m2][2 * ntp + 1];
                        mma_f16(d0[0], d0[1], d0[2], d0[3],
                                ah[m2][0], ah[m2][1], ah[m2][2], ah[m2][3],
                                bl[ntp][0], bl[ntp][1]);
                        mma_f16(d1[0], d1[1], d1[2], d1[3],
                                ah[m2][0], ah[m2][1], ah[m2][2], ah[m2][3],
                                bl[ntp][2], bl[ntp][3]);
                    }
                #pragma unroll
                for (int m2 = 0; m2 < 2; m2++)
                    #pragma unroll
                    for (int ntp = 0; ntp < 2; ntp++) {
                        float* d0 = acc[mp * 2 + m2][2 * ntp];
                        float* d1 = acc[mp * 2 + m2][2 * ntp + 1];
                        mma_f16(d0[0], d0[1], d0[2], d0[3],
                                al[m2][0], al[m2][1], al[m2][2], al[m2][3],
                                bh[ntp][0], bh[ntp][1]);
                        mma_f16(d1[0], d1[1], d1[2], d1[3],
                                al[m2][0], al[m2][1], al[m2][2], al[m2][3],
                                bh[ntp][2], bh[ntp][3]);
                    }
            }
        }
    }

    // epilogue
    const bool evenLd = ((ldD & 1) == 0);
    #pragma unroll
    for (int mt = 0; mt < 4; mt++) {
        #pragma unroll
        for (int nt = 0; nt < 4; nt++) {
            const int gn = n0 + wn * 32 + nt * 8 + 2 * t;
            if (gn >= N) continue;
            const float b0 = bias[gn];
            const float b1 = (gn + 1 < N) ? bias[gn + 1] : 0.f;
            #pragma unroll
            for (int h = 0; h < 2; h++) {
                const int gm = bm0 + wm * 64 + mt * 16 + g + h * 8;
                float v0 = acc[mt][nt][h * 2 + 0] + b0;
                float v1 = acc[mt][nt][h * 2 + 1] + b1;
                if (HAS_RES) {
                    const float* rp = Res + (long)gm * ldD + gn;
                    v0 += rp[0];
                    if (gn + 1 < N) v1 += rp[1];
                }
                if (RELU) { v0 = fmaxf(v0, 0.f); v1 = fmaxf(v1, 0.f); }
                if (QKV) {
                    float* dst;
                    if (gn < 256)      dst = Out0 + (long)gm * 256 + gn;
                    else if (gn < 512) dst = Out1 + ((long)chan * M2 + gm) * 256 + (gn - 256);
                    else               dst = Out2 + ((long)chan * M2 + gm) * 256 + (gn - 512);
                    *(float2*)dst = make_float2(v0, v1);
                } else {
                    if (OUT32) {
                        if (evenLd && gn + 1 < N) {
                            *(float2*)(Out0 + (long)gm * ldD + gn) = make_float2(v0, v1);
                        } else {
                            Out0[(long)gm * ldD + gn] = v0;
                            if (gn + 1 < N) Out0[(long)gm * ldD + gn + 1] = v1;
                        }
                    }
                    if (OUT16) {
                        const __half h0 = __float2half_rn(v0), h1 = __float2half_rn(v1);
                        const uint32_t ph = pack2(h0, h1);
                        const uint32_t pl = pack2(__float2half_rn(v0 - __half2float(h0)),
                                                  __float2half_rn(v1 - __half2float(h1)));
                        *(uint32_t*)(O16h + (long)gm * N + gn) = ph;
                        *(uint32_t*)(O16l + (long)gm * N + gn) = pl;
                    }
                }
            }
        }
    }
}

// ---------------- standalone GEMM wrapper ----------------
template<int AK, bool RELU, bool HAS_RES, bool QKV, bool OUT32, bool OUT16>
__global__ void __launch_bounds__(256, 2)
gemm_tc(const float* __restrict__ Af,
        const __half* __restrict__ Ah, const __half* __restrict__ Al,
        const __half* __restrict__ Bhi, const __half* __restrict__ Blo,
        const float* __restrict__ bias, const float* __restrict__ Res,
        float* __restrict__ Out0, float* __restrict__ Out1, float* __restrict__ Out2,
        __half* __restrict__ O16h, __half* __restrict__ O16l,
        int N, int ldD, int Ka, int Kb, int Kt, int chan, const float* gate)
{
    if (gate != nullptr && *gate < 0.5f) return;
    extern __shared__ __half smh[];
    gemm_dev<AK, RELU, HAS_RES, QKV, OUT32, OUT16>(
        Af, Ah, Al, Bhi, Blo, bias, Res, Out0, Out1, Out2, O16h, O16l,
        N, ldD, Ka, Kb, Kt, chan, blockIdx.y * 128, blockIdx.x * 128, smh);
}

// ---------------- channel attention: 2 rows/block (high occupancy) ----------------
__global__ void attn_kernel(const float* __restrict__ q, const float* __restrict__ k,
                            const float* __restrict__ v,
                            __half* __restrict__ ctxh, __half* __restrict__ ctxl,
                            int cc, const float* gate)
{
    if (*gate < 0.5f) return;
    const int wid = threadIdx.x >> 5;
    const int r = blockIdx.x * 2 + (wid >> 2);
    const int w = wid & 3;
    const int l = threadIdx.x & 31;
    const float* qp = q + (long)r * Hz + w * DHz;
    const float q0 = qp[l * 2], q1 = qp[l * 2 + 1];
    float sc[Cz];
    for (int c = 0; c < cc; c++) {
        const float* kp = k + ((long)c * M2 + r) * Hz + w * DHz;
        float p = q0 * kp[l * 2] + q1 * kp[l * 2 + 1];
        #pragma unroll
        for (int o = 16; o; o >>= 1) p += __shfl_xor_sync(0xffffffffu, p, o);
        sc[c] = p * 0.125f;
    }
    float mx = -1e30f;
    for (int c = 0; c < cc; c++) mx = fmaxf(mx, sc[c]);
    float se = 0.f;
    for (int c = 0; c < cc; c++) { sc[c] = expf(sc[c] - mx); se += sc[c]; }
    const float invs = 1.f / se;
    float o0 = 0.f, o1 = 0.f;
    for (int c = 0; c < cc; c++) {
        const float* vp = v + ((long)c * M2 + r) * Hz + w * DHz;
        const float a = sc[c] * invs;
        o0 += a * vp[l * 2]; o1 += a * vp[l * 2 + 1];
    }
    const long off = (long)r * Hz + w * DHz + l * 2;
    const __half h0 = __float2half_rn(o0), h1 = __float2half_rn(o1);
    *(uint32_t*)(ctxh + off) = pack2(h0, h1);
    *(uint32_t*)(ctxl + off) = pack2(__float2half_rn(o0 - __half2float(h0)),
                                     __float2half_rn(o1 - __half2float(h1)));
}

// ---------------- layernorm: one warp per row of 256 ----------------
__global__ void ln_kernel(const float* __restrict__ in, const float* __restrict__ g,
                          const float* __restrict__ b, float* __restrict__ out,
                          __half* __restrict__ oh, __half* __restrict__ ol,
                          const float* gate)
{
    if (*gate < 0.5f) return;
    const int r = blockIdx.x * 8 + (threadIdx.x >> 5);
    const int l = threadIdx.x & 31;
    const float* p = in + (long)r * Hz;
    float x[8]; float s = 0.f;
    #pragma unroll
    for (int j = 0; j < 8; j++) { x[j] = p[l + 32 * j]; s += x[j]; }
    #pragma unroll
    for (int o = 16; o; o >>= 1) s += __shfl_xor_sync(0xffffffffu, s, o);
    const float m = s * (1.f / 256.f);
    float vs = 0.f;
    #pragma unroll
    for (int j = 0; j < 8; j++) { const float d = x[j] - m; vs += d * d; }
    #pragma unroll
    for (int o = 16; o; o >>= 1) vs += __shfl_xor_sync(0xffffffffu, vs, o);
    const float inv = 1.f / sqrtf(vs * (1.f / 256.f) + 1e-5f);
    float* qo = out + (long)r * Hz;
    #pragma unroll
    for (int j = 0; j < 8; j++) {
        const int c = l + 32 * j;
        const float val = (x[j] - m) * inv * g[c] + b[c];
        qo[c] = val;
        const __half h = __float2half_rn(val);
        oh[(long)r * Hz + c] = h;
        ol[(long)r * Hz + c] = __float2half_rn(val - __half2float(h));
    }
}

// ---------------- ACT ponder update (standalone, gate update folded in) ----------------
__global__ void ponder_kernel(const float* __restrict__ s1, const float* __restrict__ Ws2,
                              const float* __restrict__ bs2, const float* __restrict__ ps_a,
                              const float* __restrict__ ps_b, const float* __restrict__ hh,
                              float* cum, float* rem, float* still, float* pc,
                              float* __restrict__ outacc,
                              int last, int first, float* gate, int* anyflag, int* done)
{
    if (*gate < 0.5f) return;
    const int wid  = threadIdx.x >> 5;
    const int lane = threadIdx.x & 31;
    const int r = blockIdx.x * 8 + wid;

    float p = 0.f;
    if (!last) {
        #pragma unroll
        for (int j = 0; j < 4; j++) {
            const int c = lane + 32 * j;
            p += s1[(long)r * HSz + c] * Ws2[c];
        }
    }
    #pragma unroll
    for (int o = 16; o; o >>= 1) p += __shfl_xor_sync(0xffffffffu, p, o);

    float wgt = 0.f;
    if (lane == 0) {
        float cur;
        if (last) cur = 1.f;
        else {
            const float s = p + bs2[0];
            const float z = (s - ps_a[0]) / (ps_b[0] + 1e-8f);
            cur = 1.f / (1.f + expf(-z));
        }
        const float cm = cum[r], st = still[r], rm = rem[r], p0 = pc[r];
        const float cum_n   = cm + cur * st;
        float pc_n          = p0 + st;
        const float still_n = (cum_n < 1.f - 1e-4f) ? 1.f : 0.f;
        const float rem_n   = rm - cur * still_n;
        pc_n += rem_n * (1.f - still_n);
        wgt = cur * still_n + rm * (1.f - still_n);
        cum[r] = cum_n; rem[r] = rem_n; still[r] = still_n; pc[r] = pc_n;
        if (still_n > 0.5f) *anyflag = 1;
    }
    wgt = __shfl_sync(0xffffffffu, wgt, 0);

    float4* oa = (float4*)(outacc + (long)r * Hz);
    const float4* hp = (const float4*)(hh + (long)r * Hz);
    #pragma unroll
    for (int j = 0; j < 2; j++) {
        const int i = lane * 2 + j;
        const float4 h4 = hp[i];
        if (first) {
            oa[i] = make_float4(h4.x * wgt, h4.y * wgt, h4.z * wgt, h4.w * wgt);
        } else {
            float4 o4 = oa[i];
            o4.x += h4.x * wgt; o4.y += h4.y * wgt;
            o4.z += h4.z * wgt; o4.w += h4.w * wgt;
            oa[i] = o4;
        }
    }

    __syncthreads();
    if (threadIdx.x == 0) {
        __threadfence();
        const int old = atomicAdd(done, 1);
        if (old == (int)gridDim.x - 1) {
            __threadfence();
            *gate = (*anyflag != 0) ? 1.f : 0.f;
            *anyflag = 0;
            *done = 0;
        }
    }
}

// ---------------- tail-kernel device phases (64 rows per CTA, grid 256) ----------------
__device__ void ln_dev(const float* __restrict__ in, const float* __restrict__ g,
                       const float* __restrict__ b, float* __restrict__ out,
                       __half* __restrict__ oh, __half* __restrict__ ol, int bx)
{
    const int wid = threadIdx.x >> 5;
    const int l = threadIdx.x & 31;
    #pragma unroll
    for (int j = 0; j < 8; j++) {
        const int r = bx * 64 + j * 8 + wid;
        const float* p = in + (long)r * Hz;
        float x[8]; float s = 0.f;
        #pragma unroll
        for (int q = 0; q < 8; q++) { x[q] = p[l + 32 * q]; s += x[q]; }
        #pragma unroll
        for (int o = 16; o; o >>= 1) s += __shfl_xor_sync(0xffffffffu, s, o);
        const float m = s * (1.f / 256.f);
        float vs = 0.f;
        #pragma unroll
        for (int q = 0; q < 8; q++) { const float d = x[q] - m; vs += d * d; }
        #pragma unroll
        for (int o = 16; o; o >>= 1) vs += __shfl_xor_sync(0xffffffffu, vs, o);
        const float inv = 1.f / sqrtf(vs * (1.f / 256.f) + 1e-5f);
        float* qo = out + (long)r * Hz;
        #pragma unroll
        for (int q = 0; q < 8; q++) {
            const int c = l + 32 * q;
            const float val = (x[q] - m) * inv * g[c] + b[c];
            qo[c] = val;
            const __half h = __float2half_rn(val);
            oh[(long)r * Hz + c] = h;
            ol[(long)r * Hz + c] = __float2half_rn(val - __half2float(h));
        }
    }
}

__device__ void attn_dev(const float* __restrict__ q, const float* __restrict__ k,
                         const float* __restrict__ v,
                         __half* __restrict__ ctxh, __half* __restrict__ ctxl,
                         int cc, int bx)
{
    const int wid = threadIdx.x >> 5;
    const int l = threadIdx.x & 31;
    for (int j = 0; j < 32; j++) {
        const int task = wid * 32 + j;
        const int rl = task >> 2, w = task & 3;
        const int r = bx * 64 + rl;
        const float* qp = q + (long)r * Hz + w * DHz;
        const float q0 = qp[l * 2], q1 = qp[l * 2 + 1];
        float sc[Cz];
        for (int c = 0; c < cc; c++) {
            const float* kp = k + ((long)c * M2 + r) * Hz + w * DHz;
            float p = q0 * kp[l * 2] + q1 * kp[l * 2 + 1];
            #pragma unroll
            for (int o = 16; o; o >>= 1) p += __shfl_xor_sync(0xffffffffu, p, o);
            sc[c] = p * 0.125f;
        }
        float mx = -1e30f;
        for (int c = 0; c < cc; c++) mx = fmaxf(mx, sc[c]);
        float se = 0.f;
        for (int c = 0; c < cc; c++) { sc[c] = expf(sc[c] - mx); se += sc[c]; }
        const float invs = 1.f / se;
        float o0 = 0.f, o1 = 0.f;
        for (int c = 0; c < cc; c++) {
            const float* vp = v + ((long)c * M2 + r) * Hz + w * DHz;
            const float a = sc[c] * invs;
            o0 += a * vp[l * 2]; o1 += a * vp[l * 2 + 1];
        }
        const long off = (long)r * Hz + w * DHz + l * 2;
        const __half h0 = __float2half_rn(o0), h1 = __float2half_rn(o1);
        *(uint32_t*)(ctxh + off) = pack2(h0, h1);
        *(uint32_t*)(ctxl + off) = pack2(__float2half_rn(o0 - __half2float(h0)),
                                         __float2half_rn(o1 - __half2float(h1)));
    }
}

__device__ void ponder_dev(const float* __restrict__ s1, const float* __restrict__ Ws2,
                           const float* __restrict__ bs2, const float* __restrict__ ps_a,
                           const float* __restrict__ ps_b, const float* __restrict__ hh,
                           int last, int chan, int bx)
{
    const int wid  = threadIdx.x >> 5;
    const int lane = threadIdx.x & 31;
    #pragma unroll
    for (int j = 0; j < 8; j++) {
        const int r = bx * 64 + j * 8 + wid;
        float p = 0.f;
        if (!last) {
            #pragma unroll
            for (int q = 0; q < 4; q++) {
                const int c = lane + 32 * q;
                p += s1[(long)r * HSz + c] * Ws2[c];
            }
        }
        #pragma unroll
        for (int o = 16; o; o >>= 1) p += __shfl_xor_sync(0xffffffffu, p, o);

        float wgt = 0.f;
        if (lane == 0) {
            float cur;
            if (last) cur = 1.f;
            else {
                const float s = p + bs2[0];
                const float z = (s - ps_a[0]) / (ps_b[0] + 1e-8f);
                cur = 1.f / (1.f + expf(-z));
            }
            const float cm = g_cum[r], st = g_still[r], rm = g_rem[r], p0 = g_pc[r];
            const float cum_n   = cm + cur * st;
            float pc_n          = p0 + st;
            const float still_n = (cum_n < 1.f - 1e-4f) ? 1.f : 0.f;
            const float rem_n   = rm - cur * still_n;
            pc_n += rem_n * (1.f - still_n);
            wgt = cur * still_n + rm * (1.f - still_n);
            g_cum[r] = cum_n; g_rem[r] = rem_n; g_still[r] = still_n; g_pc[r] = pc_n;
            if (still_n > 0.5f) g_any2[chan] = 1;
        }
        wgt = __shfl_sync(0xffffffffu, wgt, 0);

        float4* oa = (float4*)(g_outacc + (long)r * Hz);
        const float4* hp = (const float4*)(hh + (long)r * Hz);
        #pragma unroll
        for (int q = 0; q < 2; q++) {
            const int i = lane * 2 + q;
            const float4 h4 = hp[i];
            float4 o4 = oa[i];
            o4.x += h4.x * wgt; o4.y += h4.y * wgt;
            o4.z += h4.z * wgt; o4.w += h4.w * wgt;
            oa[i] = o4;
        }
    }
}

// ---------------- persistent tail: iterations 3..7, one launch ----------------
__global__ void __launch_bounds__(256, 2)
tail_kernel(const float* __restrict__ x, const float* __restrict__ b_in,
            const float* __restrict__ bo,
            const float* __restrict__ ln1_g, const float* __restrict__ ln1_b,
            const float* __restrict__ bf1, const float* __restrict__ bf2,
            const float* __restrict__ ln2_g, const float* __restrict__ ln2_b,
            const float* __restrict__ bs1, const float* __restrict__ Ws2,
            const float* __restrict__ bs2, const float* __restrict__ ps_a,
            const float* __restrict__ ps_b)
{
    if (g_gate[0] < 0.5f) return;     // expected path: gate died at iteration 2
    extern __shared__ __half smh[];
    const int bx = blockIdx.x;

    for (int chan = 3; chan < Cz; chan++) {
        const int last = (chan == Cz - 1) ? 1 : 0;
        const int base = (chan - 3) * 10;

        gemm_dev<1, true, false, false, true, true>(
            x, nullptr, nullptr, g_bt_in_hi, g_bt_in_lo, b_in, nullptr,
            g_lin1, nullptr, nullptr, g_lin1_h, g_lin1_l,
            256, 256, 257, 288, 9, chan, (bx >> 1) * 128, (bx & 1) * 128, smh);
        __syncthreads();
        grid_bar2(base + 0);

        for (int s = 0; s < 3; s++) {
            const int id = bx + 256 * s;
            gemm_dev<2, false, false, true, true, false>(
                nullptr, g_lin1_h, g_lin1_l, g_bt_qkv_hi, g_bt_qkv_lo, g_bqkv, nullptr,
                g_q, g_k, g_v, nullptr, nullptr,
                768, 768, 256, 256, 8, chan, (id / 6) * 128, (id % 6) * 128, smh);
            __syncthreads();
        }
        grid_bar2(base + 1);

        attn_dev(g_q, g_k, g_v, g_ctx_h, g_ctx_l, chan + 1, bx);
        grid_bar2(base + 2);

        gemm_dev<2, false, true, false, true, false>(
            nullptr, g_ctx_h, g_ctx_l, g_bt_o_hi, g_bt_o_lo, bo, g_lin1,
            g_h1pre, nullptr, nullptr, nullptr, nullptr,
            256, 256, 256, 256, 8, 0, (bx >> 1) * 128, (bx & 1) * 128, smh);
        __syncthreads();
        grid_bar2(base + 3);

        ln_dev(g_h1pre, ln1_g, ln1_b, g_h1, g_h1_h, g_h1_l, bx);
        grid_bar2(base + 4);

        for (int s = 0; s < 2; s++) {
            const int id = bx + 256 * s;
            gemm_dev<2, true, false, false, false, true>(
                nullptr, g_h1_h, g_h1_l, g_bt_f1_hi, g_bt_f1_lo, bf1, nullptr,
                nullptr, nullptr, nullptr, g_f1_h, g_f1_l,
                512, 512, 256, 256, 8, 0, (id / 4) * 128, (id % 4) * 128, smh);
            __syncthreads();
        }
        grid_bar2(base + 5);

        gemm_dev<2, false, true, false, true, false>(
            nullptr, g_f1_h, g_f1_l, g_bt_f2_hi, g_bt_f2_lo, bf2, g_h1,
            g_hhpre, nullptr, nullptr, nullptr, nullptr,
            256, 256, 512, 512, 16, 0, (bx >> 1) * 128, (bx & 1) * 128, smh);
        __syncthreads();
        grid_bar2(base + 6);

        ln_dev(g_hhpre, ln2_g, ln2_b, g_hh, g_hh_h, g_hh_l, bx);
        grid_bar2(base + 7);

        if (!last && bx < 128) {
            gemm_dev<2, true, false, false, true, false>(
                nullptr, g_hh_h, g_hh_l, g_bt_s1_hi, g_bt_s1_lo, bs1, nullptr,
                g_s1, nullptr, nullptr, nullptr, nullptr,
                128, 128, 256, 256, 8, 0, bx * 128, 0, smh);
            __syncthreads();
        }
        grid_bar2(base + 8);

        ponder_dev(g_s1, Ws2, bs2, ps_a, ps_b, g_hh, last, chan, bx);
        grid_bar2(base + 9);

        if (g_any2[chan] == 0) break;   // all rows halted: stop (race-free: set before barrier)
    }
}

// ---------------- one-shot prep ----------------
__global__ void prep_kernel(const float* __restrict__ W_in, const float* __restrict__ Wq,
                            const float* __restrict__ Wk, const float* __restrict__ Wv,
                            const float* __restrict__ Wo, const float* __restrict__ Wf1,
                            const float* __restrict__ Wf2, const float* __restrict__ Ws1,
                            const float* __restrict__ W_out,
                            const float* __restrict__ bq, const float* __restrict__ bk,
                            const float* __restrict__ bv)
{
    const int i = blockIdx.x * 256 + threadIdx.x;
    float v; int li;
    __half *dh, *dl;
    if (i < 73728) {            // W_in: K=257 N=256 Kpad=288
        li = i; const int n = li / 288, k = li % 288;
        v = (k < 257) ? W_in[(long)k * 256 + n] : 0.f;
        dh = g_bt_in_hi; dl = g_bt_in_lo;
    } else if (i < 139264) {    // Wq
        li = i - 73728; const int n = li / 256, k = li % 256;
        v = Wq[(long)k * 256 + n];
        dh = g_bt_qkv_hi; dl = g_bt_qkv_lo;
    } else if (i < 204800) {    // Wk
        li = i - 139264; const int n = li / 256, k = li % 256;
        v = Wk[(long)k * 256 + n];
        dh = g_bt_qkv_hi + 65536; dl = g_bt_qkv_lo + 65536;
    } else if (i < 270336) {    // Wv
        li = i - 204800; const int n = li / 256, k = li % 256;
        v = Wv[(long)k * 256 + n];
        dh = g_bt_qkv_hi + 131072; dl = g_bt_qkv_lo + 131072;
    } else if (i < 335872) {    // Wo
        li = i - 270336; const int n = li / 256, k = li % 256;
        v = Wo[(long)k * 256 + n];
        dh = g_bt_o_hi; dl = g_bt_o_lo;
    } else if (i < 466944) {    // Wf1: K=256 N=512
        li = i - 335872; const int n = li / 256, k = li % 256;
        v = Wf1[(long)k * 512 + n];
        dh = g_bt_f1_hi; dl = g_bt_f1_lo;
    } else if (i < 598016) {    // Wf2: K=512 N=256
        li = i - 466944; const int n = li / 512, k = li % 512;
        v = Wf2[(long)k * 256 + n];
        dh = g_bt_f2_hi; dl = g_bt_f2_lo;
    } else if (i < 630784) {    // Ws1: K=256 N=128
        li = i - 598016; const int n = li / 256, k = li % 256;
        v = Ws1[(long)k * 128 + n];
        dh = g_bt_s1_hi; dl = g_bt_s1_lo;
    } else if (i < 696320) {    // W_out cols 0..255
        li = i - 630784; const int n = li / 256, k = li % 256;
        v = W_out[(long)k * 257 + n];
        dh = g_bt_out_hi; dl = g_bt_out_lo;
    } else if (i < 697088) {    // bqkv
        const int j = i - 696320;
        g_bqkv[j] = (j < 256) ? bq[j] : ((j < 512) ? bk[j - 256] : bv[j - 512]);
        return;
    } else if (i < 713472) {    // per-row ACT state + flags
        const int r = i - 697088;
        g_cum[r] = 0.f; g_rem[r] = 1.f; g_still[r] = 1.f; g_pc[r] = 0.f;
        if (r < 64) g_bar2[r] = 0;
        if (r < 8)  g_any2[r] = 0;
        if (r == 0) { g_gate[0] = 1.f; g_any[0] = 0; g_done[0] = 0; }
        return;
    } else return;
    const __half h = __float2half_rn(v);
    dh[li] = h;
    dl[li] = __float2half_rn(v - __half2float(h));
}

// ---------------- final column 256 GEMV + pc writeout ----------------
__global__ void gemv_pc_kernel(float* __restrict__ out, const float* __restrict__ outacc,
                               const float* __restrict__ W_out, const float* __restrict__ b_out,
                               const float* __restrict__ pc)
{
    __shared__ float wc[256];
    const int tid = threadIdx.x;
    wc[tid] = W_out[(long)tid * 257 + 256];
    __syncthreads();
    const float bb = b_out[256];
    const int wid = tid >> 5, lane = tid & 31;

    for (int j = 0; j < 32; j++) {
        const int r = blockIdx.x * 256 + j * 8 + wid;
        const float4* ap = (const float4*)(outacc + (long)r * Hz);
        float dot = 0.f;
        #pragma unroll
        for (int q = 0; q < 2; q++) {
            const int base = lane * 8 + q * 4;
            const float4 a4 = ap[lane * 2 + q];
            dot += a4.x * wc[base] + a4.y * wc[base + 1] + a4.z * wc[base + 2] + a4.w * wc[base + 3];
        }
        #pragma unroll
        for (int o = 16; o; o >>= 1) dot += __shfl_xor_sync(0xffffffffu, dot, o);
        if (lane == 0) out[(long)r * 257 + 256] = fmaxf(dot + bb, 0.f);
    }
    const int r = blockIdx.x * 256 + tid;
    out[BTF + r] = pc[r];
}

// ---------------- host launch ----------------
static void* symA(const void* s)
{
    void* p = nullptr;
    cudaGetSymbolAddress(&p, s);
    return p;
}

extern "C" void kernel_launch(void* const* d_in, const int* in_sizes, int n_in,
                              void* d_out, int out_size)
{
    const float* x     = (const float*)d_in[0];
    const float* W_in  = (const float*)d_in[1];
    const float* b_in  = (const float*)d_in[2];
    const float* W_out = (const float*)d_in[3];
    const float* b_out = (const float*)d_in[4];
    const float* Wq    = (const float*)d_in[5];
    const float* bq    = (const float*)d_in[6];
    const float* Wk    = (const float*)d_in[7];
    const float* bk    = (const float*)d_in[8];
    const float* Wv    = (const float*)d_in[9];
    const float* bv    = (const float*)d_in[10];
    const float* Wo    = (const float*)d_in[11];
    const float* bo    = (const float*)d_in[12];
    const float* ln1_g = (const float*)d_in[13];
    const float* ln1_b = (const float*)d_in[14];
    const float* Wf1   = (const float*)d_in[15];
    const float* bf1   = (const float*)d_in[16];
    const float* Wf2   = (const float*)d_in[17];
    const float* bf2   = (const float*)d_in[18];
    const float* ln2_g = (const float*)d_in[19];
    const float* ln2_b = (const float*)d_in[20];
    const float* Ws1   = (const float*)d_in[21];
    const float* bs1   = (const float*)d_in[22];
    const float* Ws2   = (const float*)d_in[23];
    const float* bs2   = (const float*)d_in[24];
    const float* ps_a  = (const float*)d_in[25];
    const float* ps_b  = (const float*)d_in[26];
    float* out = (float*)d_out;

    float* p_lin1  = (float*)symA(g_lin1);
    float* p_q     = (float*)symA(g_q);
    float* p_k     = (float*)symA(g_k);
    float* p_v     = (float*)symA(g_v);
    float* p_h1pre = (float*)symA(g_h1pre);
    float* p_h1    = (float*)symA(g_h1);
    float* p_hhpre = (float*)symA(g_hhpre);
    float* p_hh    = (float*)symA(g_hh);
    float* p_s1    = (float*)symA(g_s1);
    float* p_oacc  = (float*)symA(g_outacc);
    float* p_cum   = (float*)symA(g_cum);
    float* p_rem   = (float*)symA(g_rem);
    float* p_still = (float*)symA(g_still);
    float* p_pc    = (float*)symA(g_pc);
    float* p_bqkv  = (float*)symA(g_bqkv);
    float* p_gate  = (float*)symA(g_gate);
    int*   p_any   = (int*)symA(g_any);
    int*   p_done  = (int*)symA(g_done);

    __half* lin1_h = (__half*)symA(g_lin1_h), *lin1_l = (__half*)symA(g_lin1_l);
    __half* ctx_h  = (__half*)symA(g_ctx_h),  *ctx_l  = (__half*)symA(g_ctx_l);
    __half* h1_h   = (__half*)symA(g_h1_h),   *h1_l   = (__half*)symA(g_h1_l);
    __half* f1a_h  = (__half*)symA(g_f1_h),   *f1a_l  = (__half*)symA(g_f1_l);
    __half* hh_h   = (__half*)symA(g_hh_h),   *hh_l   = (__half*)symA(g_hh_l);

    __half* bt_in_h  = (__half*)symA(g_bt_in_hi),  *bt_in_l  = (__half*)symA(g_bt_in_lo);
    __half* bt_qkv_h = (__half*)symA(g_bt_qkv_hi), *bt_qkv_l = (__half*)symA(g_bt_qkv_lo);
    __half* bt_o_h   = (__half*)symA(g_bt_o_hi),   *bt_o_l   = (__half*)symA(g_bt_o_lo);
    __half* bt_f1_h  = (__half*)symA(g_bt_f1_hi),  *bt_f1_l  = (__half*)symA(g_bt_f1_lo);
    __half* bt_f2_h  = (__half*)symA(g_bt_f2_hi),  *bt_f2_l  = (__half*)symA(g_bt_f2_lo);
    __half* bt_s1_h  = (__half*)symA(g_bt_s1_hi),  *bt_s1_l  = (__half*)symA(g_bt_s1_lo);
    __half* bt_out_h = (__half*)symA(g_bt_out_hi), *bt_out_l = (__half*)symA(g_bt_out_lo);

    cudaFuncSetAttribute((const void*)gemm_tc<1, true,  false, false, true,  true >,
                         cudaFuncAttributeMaxDynamicSharedMemorySize, SMEM_DYN);
    cudaFuncSetAttribute((const void*)gemm_tc<2, false, false, true,  true,  false>,
                         cudaFuncAttributeMaxDynamicSharedMemorySize, SMEM_DYN);
    cudaFuncSetAttribute((const void*)gemm_tc<2, false, true,  false, true,  false>,
                         cudaFuncAttributeMaxDynamicSharedMemorySize, SMEM_DYN);
    cudaFuncSetAttribute((const void*)gemm_tc<2, true,  false, false, false, true >,
                         cudaFuncAttributeMaxDynamicSharedMemorySize, SMEM_DYN);
    cudaFuncSetAttribute((const void*)gemm_tc<2, true,  false, false, true,  false>,
                         cudaFuncAttributeMaxDynamicSharedMemorySize, SMEM_DYN);
    cudaFuncSetAttribute((const void*)gemm_tc<0, true,  false, false, true,  false>,
                         cudaFuncAttributeMaxDynamicSharedMemorySize, SMEM_DYN);
    cudaFuncSetAttribute((const void*)tail_kernel,
                         cudaFuncAttributeMaxDynamicSharedMemorySize, SMEM_DYN);

    // one-shot prep
    prep_kernel<<<2788, 256>>>(W_in, Wq, Wk, Wv, Wo, Wf1, Wf2, Ws1, W_out, bq, bk, bv);

    // iterations 0..2: separate high-occupancy kernels (expected live)
    for (int ci = 0; ci < 3; ci++) {
        gemm_tc<1, true, false, false, true, true><<<dim3(2, 128), 256, SMEM_DYN>>>(
            x, nullptr, nullptr, bt_in_h, bt_in_l, b_in, nullptr,
            p_lin1, nullptr, nullptr, lin1_h, lin1_l,
            256, 256, 257, 288, 9, ci, p_gate);
        gemm_tc<2, false, false, true, true, false><<<dim3(6, 128), 256, SMEM_DYN>>>(
            nullptr, lin1_h, lin1_l, bt_qkv_h, bt_qkv_l, p_bqkv, nullptr,
            p_q, p_k, p_v, nullptr, nullptr,
            768, 768, 256, 256, 8, ci, p_gate);
        attn_kernel<<<8192, 256>>>(p_q, p_k, p_v, ctx_h, ctx_l, ci + 1, p_gate);
        gemm_tc<2, false, true, false, true, false><<<dim3(2, 128), 256, SMEM_DYN>>>(
            nullptr, ctx_h, ctx_l, bt_o_h, bt_o_l, bo, p_lin1,
            p_h1pre, nullptr, nullptr, nullptr, nullptr,
            256, 256, 256, 256, 8, 0, p_gate);
        ln_kernel<<<2048, 256>>>(p_h1pre, ln1_g, ln1_b, p_h1, h1_h, h1_l, p_gate);
        gemm_tc<2, true, false, false, false, true><<<dim3(4, 128), 256, SMEM_DYN>>>(
            nullptr, h1_h, h1_l, bt_f1_h, bt_f1_l, bf1, nullptr,
            nullptr, nullptr, nullptr, f1a_h, f1a_l,
            512, 512, 256, 256, 8, 0, p_gate);
        gemm_tc<2, false, true, false, true, false><<<dim3(2, 128), 256, SMEM_DYN>>>(
            nullptr, f1a_h, f1a_l, bt_f2_h, bt_f2_l, bf2, p_h1,
            p_hhpre, nullptr, nullptr, nullptr, nullptr,
            256, 256, 512, 512, 16, 0, p_gate);
        ln_kernel<<<2048, 256>>>(p_hhpre, ln2_g, ln2_b, p_hh, hh_h, hh_l, p_gate);
        gemm_tc<2, true, false, false, true, false><<<dim3(1, 128), 256, SMEM_DYN>>>(
            nullptr, hh_h, hh_l, bt_s1_h, bt_s1_l, bs1, nullptr,
            p_s1, nullptr, nullptr, nullptr, nullptr,
            128, 128, 256, 256, 8, 0, p_gate);
        ponder_kernel<<<2048, 256>>>(p_s1, Ws2, bs2, ps_a, ps_b, p_hh,
                                     p_cum, p_rem, p_still, p_pc, p_oacc,
                                     0, (ci == 0) ? 1 : 0,
                                     p_gate, p_any, p_done);
    }

    // iterations 3..7: single persistent tail launch (early-exits if gate dead)
    tail_kernel<<<256, 256, SMEM_DYN>>>(
        x, b_in, bo, ln1_g, ln1_b, bf1, bf2, ln2_g, ln2_b,
        bs1, Ws2, bs2, ps_a, ps_b);

    // encoder_out cols 0..255 (ldD = 257)
    gemm_tc<0, true, false, false, true, false><<<dim3(2, 128), 256, SMEM_DYN>>>(
        p_oacc, nullptr, nullptr, bt_out_h, bt_out_l, b_out, nullptr,
        out, nullptr, nullptr, nullptr, nullptr,
        256, 257, 256, 256, 8, 0, nullptr);
    // col 256 GEMV + pc writeout
    gemv_pc_kernel<<<64, 256>>>(out, p_oacc, W_out, b_out, p_pc);
}